// round 3
// baseline (speedup 1.0000x reference)
#include <cuda_runtime.h>

#define NB 16
#define SEQ 1024
#define DM 512
#define NH 8
#define HD 64
#define NROWS (NB*SEQ)          // 16384
#define OUT0 (NROWS*DM)         // 8388608 floats: out region, then weights

#define SQ_STR 68               // smem stride for 64-wide tiles (conflict-free frag loads)
#define SS_STR 1028             // smem stride for 1024-wide score rows

__device__ float g_q[NROWS*DM];
__device__ float g_k[NROWS*DM];
__device__ float g_v[NROWS*DM];
__device__ float g_att[NROWS*DM];
__device__ int   g_valid[NROWS];

#define NEGINF __int_as_float(0xff800000)

__device__ __forceinline__ unsigned f2tf(float x){
    unsigned r; asm("cvt.rna.tf32.f32 %0, %1;" : "=r"(r) : "f"(x)); return r;
}

// D += A(16x8 row) * B(8x8 col), tf32 in, fp32 accum
__device__ __forceinline__ void mma8(float c[4], const unsigned a[4], const unsigned b[2]){
    asm volatile("mma.sync.aligned.m16n8k8.row.col.f32.tf32.tf32.f32 "
        "{%0,%1,%2,%3}, {%4,%5,%6,%7}, {%8,%9}, {%0,%1,%2,%3};\n"
        : "+f"(c[0]), "+f"(c[1]), "+f"(c[2]), "+f"(c[3])
        : "r"(a[0]), "r"(a[1]), "r"(a[2]), "r"(a[3]), "r"(b[0]), "r"(b[1]));
}

// ---------------------------------------------------------------------------
// Kernel 1: per-row validity (row is padding iff all 512 features == 0)
// ---------------------------------------------------------------------------
__global__ void valid_kernel(const float* __restrict__ Q){
    int row  = blockIdx.x * 8 + (threadIdx.x >> 5);
    int lane = threadIdx.x & 31;
    const float4* p = (const float4*)(Q + (size_t)row * DM);
    bool nz = false;
    #pragma unroll
    for (int i = 0; i < 4; i++){
        float4 v = p[lane + i*32];
        nz |= (v.x != 0.f) || (v.y != 0.f) || (v.z != 0.f) || (v.w != 0.f);
    }
    unsigned m = __ballot_sync(0xffffffffu, nz);
    if (lane == 0) g_valid[row] = (m != 0u);
}

// ---------------------------------------------------------------------------
// Kernel 2: QKV projection  out = relu(Q @ W^T + b), tf32 mma
// Block tile 128x64, BK=32; 8 warps as 4x2, warp tile 32x32 (2 m16 x 4 n8)
// blockIdx.z in {0,1,2} selects (Wq,bq,g_q)/(Wk,..)/(Wv,..)
// ---------------------------------------------------------------------------
__global__ __launch_bounds__(256) void proj_kernel(
    const float* __restrict__ Q,
    const float* __restrict__ Wq, const float* __restrict__ bq,
    const float* __restrict__ Wk, const float* __restrict__ bk,
    const float* __restrict__ Wv, const float* __restrict__ bv)
{
    __shared__ unsigned As[128*36];
    __shared__ unsigned Bs[64*36];

    const int z = blockIdx.z;
    const float* W    = (z==0) ? Wq : (z==1) ? Wk : Wv;
    const float* bias = (z==0) ? bq : (z==1) ? bk : bv;
    float*       out  = (z==0) ? g_q : (z==1) ? g_k : g_v;

    const int m0 = blockIdx.y * 128, n0 = blockIdx.x * 64;
    const int tid = threadIdx.x, warp = tid >> 5, lane = tid & 31;
    const int wm = warp >> 1, wn = warp & 1;

    float acc[2][4][4];
    #pragma unroll
    for (int i=0;i<2;i++)
        #pragma unroll
        for (int j=0;j<4;j++)
            #pragma unroll
            for (int r=0;r<4;r++) acc[i][j][r] = 0.f;

    const int ar = tid >> 3, ac = (tid & 7) * 4;

    for (int kt = 0; kt < DM; kt += 32){
        #pragma unroll
        for (int i = 0; i < 4; i++){
            int r = ar + i*32;
            float4 v = *(const float4*)(Q + (m0 + r)*DM + kt + ac);
            unsigned* s = &As[r*36 + ac];
            s[0]=f2tf(v.x); s[1]=f2tf(v.y); s[2]=f2tf(v.z); s[3]=f2tf(v.w);
        }
        #pragma unroll
        for (int i = 0; i < 2; i++){
            int r = ar + i*32;
            float4 v = *(const float4*)(W + (n0 + r)*DM + kt + ac);
            unsigned* s = &Bs[r*36 + ac];
            s[0]=f2tf(v.x); s[1]=f2tf(v.y); s[2]=f2tf(v.z); s[3]=f2tf(v.w);
        }
        __syncthreads();
        #pragma unroll
        for (int ks = 0; ks < 32; ks += 8){
            unsigned a[2][4], b[4][2];
            const int cb = ks + (lane & 3);
            #pragma unroll
            for (int mi = 0; mi < 2; mi++){
                int r0 = wm*32 + mi*16 + (lane >> 2);
                a[mi][0] = As[ r0   *36 + cb];
                a[mi][1] = As[(r0+8)*36 + cb];
                a[mi][2] = As[ r0   *36 + cb + 4];
                a[mi][3] = As[(r0+8)*36 + cb + 4];
            }
            #pragma unroll
            for (int ni = 0; ni < 4; ni++){
                int c0 = wn*32 + ni*8 + (lane >> 2);
                b[ni][0] = Bs[c0*36 + cb];
                b[ni][1] = Bs[c0*36 + cb + 4];
            }
            #pragma unroll
            for (int mi = 0; mi < 2; mi++)
                #pragma unroll
                for (int ni = 0; ni < 4; ni++)
                    mma8(acc[mi][ni], a[mi], b[ni]);
        }
        __syncthreads();
    }

    #pragma unroll
    for (int mi = 0; mi < 2; mi++){
        #pragma unroll
        for (int ni = 0; ni < 4; ni++){
            int row = m0 + wm*32 + mi*16 + (lane >> 2);
            int col = n0 + wn*32 + ni*8 + (lane & 3)*2;
            float b0 = __ldg(bias + col), b1 = __ldg(bias + col + 1);
            *(float2*)(out + (size_t)row*DM + col) =
                make_float2(fmaxf(acc[mi][ni][0] + b0, 0.f),
                            fmaxf(acc[mi][ni][1] + b1, 0.f));
            *(float2*)(out + (size_t)(row+8)*DM + col) =
                make_float2(fmaxf(acc[mi][ni][2] + b0, 0.f),
                            fmaxf(acc[mi][ni][3] + b1, 0.f));
        }
    }
}

// ---------------------------------------------------------------------------
// Kernel 3: attention per (b, h, 32-row q-tile)
//   phase 1: scores = (qh @ kh^T)/8 with mask -> smem [32][1024]
//   phase 2: exact softmax per row, write weights to d_out, keep tf32 in smem
//   phase 3: attn = w @ vh, + residual qh, -> g_att
// 8 warps as 2x4, warp tile 16x16 (1 m16 x 2 n8)
// ---------------------------------------------------------------------------
__global__ __launch_bounds__(256) void attn_kernel(float* __restrict__ wout){
    extern __shared__ unsigned smem[];
    unsigned* sQ  = smem;                         // 32 * 68
    unsigned* sKV = sQ + 32*SQ_STR;               // 64 * 68  (K, then V^T)
    float*    sS  = (float*)(sKV + 64*SQ_STR);    // 32 * 1028
    int*      sVK = (int*)(sS + 32*SS_STR);       // 64
    int*      sVQ = sVK + 64;                     // 32

    const int b = blockIdx.z, h = blockIdx.y;
    const int q0 = blockIdx.x * 32;
    const int tid = threadIdx.x, warp = tid >> 5, lane = tid & 31;
    const int rowbase = b * SEQ;
    const int wm = warp >> 2, wn = warp & 3;

    // load Q tile [32 x 64] (tf32)
    for (int i = tid; i < 512; i += 256){
        int r = i >> 4, c = (i & 15) * 4;
        float4 v = *(const float4*)(g_q + (size_t)(rowbase + q0 + r)*DM + h*HD + c);
        unsigned* s = &sQ[r*SQ_STR + c];
        s[0]=f2tf(v.x); s[1]=f2tf(v.y); s[2]=f2tf(v.z); s[3]=f2tf(v.w);
    }
    if (tid < 32) sVQ[tid] = g_valid[rowbase + q0 + tid];

    // ---- phase 1: scores ----
    for (int kt = 0; kt < 16; kt++){
        const int k0 = kt * 64;
        for (int i = tid; i < 1024; i += 256){
            int r = i >> 4, c = (i & 15) * 4;
            float4 v = *(const float4*)(g_k + (size_t)(rowbase + k0 + r)*DM + h*HD + c);
            unsigned* s = &sKV[r*SQ_STR + c];
            s[0]=f2tf(v.x); s[1]=f2tf(v.y); s[2]=f2tf(v.z); s[3]=f2tf(v.w);
        }
        if (tid < 64) sVK[tid] = g_valid[rowbase + k0 + tid];
        __syncthreads();

        float c2[2][4] = {{0,0,0,0},{0,0,0,0}};
        #pragma unroll
        for (int ks = 0; ks < 64; ks += 8){
            unsigned a[4], bf[2][2];
            const int cb = ks + (lane & 3);
            int r0 = wm*16 + (lane >> 2);
            a[0]=sQ[ r0   *SQ_STR + cb];   a[1]=sQ[(r0+8)*SQ_STR + cb];
            a[2]=sQ[ r0   *SQ_STR + cb+4]; a[3]=sQ[(r0+8)*SQ_STR + cb+4];
            #pragma unroll
            for (int ni = 0; ni < 2; ni++){
                int c0 = wn*16 + ni*8 + (lane >> 2);
                bf[ni][0] = sKV[c0*SQ_STR + cb];
                bf[ni][1] = sKV[c0*SQ_STR + cb + 4];
            }
            mma8(c2[0], a, bf[0]);
            mma8(c2[1], a, bf[1]);
        }
        #pragma unroll
        for (int ni = 0; ni < 2; ni++){
            int r  = wm*16 + (lane >> 2);
            int cl = wn*16 + ni*8 + (lane & 3)*2;
            bool v0 = sVK[cl] != 0, v1 = sVK[cl+1] != 0;
            sS[ r   *SS_STR + k0 + cl    ] = v0 ? c2[ni][0]*0.125f : NEGINF;
            sS[ r   *SS_STR + k0 + cl + 1] = v1 ? c2[ni][1]*0.125f : NEGINF;
            sS[(r+8)*SS_STR + k0 + cl    ] = v0 ? c2[ni][2]*0.125f : NEGINF;
            sS[(r+8)*SS_STR + k0 + cl + 1] = v1 ? c2[ni][3]*0.125f : NEGINF;
        }
        __syncthreads();
    }

    // ---- phase 2: softmax (one warp owns 4 rows) ----
    #pragma unroll 1
    for (int rr = 0; rr < 4; rr++){
        int r = warp*4 + rr;
        float* srow = sS + r*SS_STR;
        bool vq = sVQ[r] != 0;
        float vals[32];
        float m = NEGINF;
        #pragma unroll
        for (int j = 0; j < 32; j++){ vals[j] = srow[lane + j*32]; m = fmaxf(m, vals[j]); }
        #pragma unroll
        for (int o = 16; o > 0; o >>= 1) m = fmaxf(m, __shfl_xor_sync(0xffffffffu, m, o));
        float sum = 0.f;
        #pragma unroll
        for (int j = 0; j < 32; j++){ float p = __expf(vals[j] - m); vals[j] = p; sum += p; }
        #pragma unroll
        for (int o = 16; o > 0; o >>= 1) sum += __shfl_xor_sync(0xffffffffu, sum, o);
        float rs = 1.f / sum;
        float* gw = wout + ((size_t)((b*NH + h)*SEQ + q0 + r)) * SEQ;
        unsigned* srowu = (unsigned*)srow;
        #pragma unroll
        for (int j = 0; j < 32; j++){
            float w = vq ? vals[j]*rs : 0.f;   // invalid q-row: nan_to_num -> 0
            gw[lane + j*32]    = w;
            srowu[lane + j*32] = f2tf(w);
        }
    }
    __syncthreads();

    // ---- phase 3: attn = w @ V (+ residual) ----
    float acc[2][4] = {{0,0,0,0},{0,0,0,0}};
    for (int kt = 0; kt < 16; kt++){
        const int k0 = kt * 64;
        for (int i = tid; i < 1024; i += 256){   // V transposed into smem: sKV[d][s]
            int r = i >> 4, c = (i & 15) * 4;
            float4 v = *(const float4*)(g_v + (size_t)(rowbase + k0 + r)*DM + h*HD + c);
            sKV[(c+0)*SQ_STR + r] = f2tf(v.x);
            sKV[(c+1)*SQ_STR + r] = f2tf(v.y);
            sKV[(c+2)*SQ_STR + r] = f2tf(v.z);
            sKV[(c+3)*SQ_STR + r] = f2tf(v.w);
        }
        __syncthreads();
        const unsigned* sSu = (const unsigned*)sS;
        #pragma unroll
        for (int ks = 0; ks < 64; ks += 8){
            unsigned a[4], bf[2][2];
            int r0 = wm*16 + (lane >> 2);
            int cb = k0 + ks + (lane & 3);
            a[0]=sSu[ r0   *SS_STR + cb];   a[1]=sSu[(r0+8)*SS_STR + cb];
            a[2]=sSu[ r0   *SS_STR + cb+4]; a[3]=sSu[(r0+8)*SS_STR + cb+4];
            #pragma unroll
            for (int ni = 0; ni < 2; ni++){
                int c0 = wn*16 + ni*8 + (lane >> 2);
                bf[ni][0] = sKV[c0*SQ_STR + ks + (lane & 3)];
                bf[ni][1] = sKV[c0*SQ_STR + ks + (lane & 3) + 4];
            }
            mma8(acc[0], a, bf[0]);
            mma8(acc[1], a, bf[1]);
        }
        __syncthreads();
    }
    #pragma unroll
    for (int ni = 0; ni < 2; ni++){
        int r  = q0 + wm*16 + (lane >> 2);
        int cl = h*HD + wn*16 + ni*8 + (lane & 3)*2;
        size_t base = (size_t)(rowbase + r)*DM + cl;
        float2 r0v = *(const float2*)(g_q + base);
        float2 r1v = *(const float2*)(g_q + base + 8*DM);
        *(float2*)(g_att + base)        = make_float2(acc[ni][0] + r0v.x, acc[ni][1] + r0v.y);
        *(float2*)(g_att + base + 8*DM) = make_float2(acc[ni][2] + r1v.x, acc[ni][3] + r1v.y);
    }
}

// ---------------------------------------------------------------------------
// Kernel 4: LayerNorm + relu, one block (128 thr) per row
// ---------------------------------------------------------------------------
__global__ __launch_bounds__(128) void ln_kernel(const float* __restrict__ lnw,
                                                 const float* __restrict__ lnb,
                                                 float* __restrict__ out){
    const int row = blockIdx.x, tid = threadIdx.x;
    const float4 x = *(const float4*)(g_att + (size_t)row*DM + tid*4);
    float s  = x.x + x.y + x.z + x.w;
    float ss = fmaf(x.x, x.x, fmaf(x.y, x.y, fmaf(x.z, x.z, x.w*x.w)));
    #pragma unroll
    for (int o = 16; o > 0; o >>= 1){
        s  += __shfl_xor_sync(0xffffffffu, s,  o);
        ss += __shfl_xor_sync(0xffffffffu, ss, o);
    }
    __shared__ float red[8];
    int warp = tid >> 5, lane = tid & 31;
    if (lane == 0){ red[warp] = s; red[warp+4] = ss; }
    __syncthreads();
    s  = red[0] + red[1] + red[2] + red[3];
    ss = red[4] + red[5] + red[6] + red[7];
    float mu  = s * (1.0f/DM);
    float inv = rsqrtf(ss * (1.0f/DM) - mu*mu + 1e-5f);
    const float4 w = *(const float4*)(lnw + tid*4);
    const float4 bb = *(const float4*)(lnb + tid*4);
    float4 y;
    y.x = fmaxf((x.x - mu)*inv*w.x + bb.x, 0.f);
    y.y = fmaxf((x.y - mu)*inv*w.y + bb.y, 0.f);
    y.z = fmaxf((x.z - mu)*inv*w.z + bb.z, 0.f);
    y.w = fmaxf((x.w - mu)*inv*w.w + bb.w, 0.f);
    *(float4*)(out + (size_t)row*DM + tid*4) = y;
}

// ---------------------------------------------------------------------------
extern "C" void kernel_launch(void* const* d_in, const int* in_sizes, int n_in,
                              void* d_out, int out_size){
    const float* Q   = (const float*)d_in[0];
    const float* Wq  = (const float*)d_in[1];
    const float* bq  = (const float*)d_in[2];
    const float* Wk  = (const float*)d_in[3];
    const float* bk  = (const float*)d_in[4];
    const float* Wv  = (const float*)d_in[5];
    const float* bv  = (const float*)d_in[6];
    const float* lnw = (const float*)d_in[7];
    const float* lnb = (const float*)d_in[8];
    float* out = (float*)d_out;

    valid_kernel<<<NROWS/8, 256>>>(Q);
    proj_kernel<<<dim3(8, 128, 3), 256>>>(Q, Wq, bq, Wk, bk, Wv, bv);

    const int smem_bytes = (32*SQ_STR + 64*SQ_STR + 32*SS_STR + 96) * 4;  // 158080
    cudaFuncSetAttribute(attn_kernel, cudaFuncAttributeMaxDynamicSharedMemorySize, smem_bytes);
    attn_kernel<<<dim3(SEQ/32, NH, NB), 256, smem_bytes>>>(out + OUT0);

    ln_kernel<<<NROWS, 128>>>(lnw, lnb, out);
}

// round 4
// speedup vs baseline: 3.0355x; 3.0355x over previous
#include <cuda_runtime.h>

#define NB 16
#define SEQ 1024
#define DM 512
#define NH 8
#define HD 64
#define NROWS (NB*SEQ)          // 16384
#define OUT0 (NROWS*DM)         // 8388608 floats: out region, then weights

#define SQ_STR 68               // smem stride, conflict-free a/b frag loads ([m][k]/[n][k])
#define SV_STR 72               // smem stride for V in [k][n] layout (≡8 mod 32)
#define SS_STR 1028             // smem stride for 1024-wide score rows

__device__ float g_q[NROWS*DM];
__device__ float g_k[NROWS*DM];
__device__ float g_v[NROWS*DM];
__device__ float g_att[NROWS*DM];
__device__ int   g_valid[NROWS];

#define NEGINF __int_as_float(0xff800000)

__device__ __forceinline__ unsigned f2tf(float x){
    unsigned r; asm("cvt.rna.tf32.f32 %0, %1;" : "=r"(r) : "f"(x)); return r;
}
__device__ __forceinline__ uint4 f2tf4(float4 v){
    return make_uint4(f2tf(v.x), f2tf(v.y), f2tf(v.z), f2tf(v.w));
}

// D += A(16x8 row) * B(8x8 col), tf32 in, fp32 accum
__device__ __forceinline__ void mma8(float c[4], const unsigned a[4], const unsigned b[2]){
    asm volatile("mma.sync.aligned.m16n8k8.row.col.f32.tf32.tf32.f32 "
        "{%0,%1,%2,%3}, {%4,%5,%6,%7}, {%8,%9}, {%0,%1,%2,%3};\n"
        : "+f"(c[0]), "+f"(c[1]), "+f"(c[2]), "+f"(c[3])
        : "r"(a[0]), "r"(a[1]), "r"(a[2]), "r"(a[3]), "r"(b[0]), "r"(b[1]));
}

// ---------------------------------------------------------------------------
// Kernel 1: per-row validity (row is padding iff all 512 features == 0)
// ---------------------------------------------------------------------------
__global__ void valid_kernel(const float* __restrict__ Q){
    int row  = blockIdx.x * 8 + (threadIdx.x >> 5);
    int lane = threadIdx.x & 31;
    const float4* p = (const float4*)(Q + (size_t)row * DM);
    bool nz = false;
    #pragma unroll
    for (int i = 0; i < 4; i++){
        float4 v = p[lane + i*32];
        nz |= (v.x != 0.f) || (v.y != 0.f) || (v.z != 0.f) || (v.w != 0.f);
    }
    unsigned m = __ballot_sync(0xffffffffu, nz);
    if (lane == 0) g_valid[row] = (m != 0u);
}

// ---------------------------------------------------------------------------
// Kernel 2: QKV projection  out = relu(Q @ W^T + b), tf32 mma
// Block tile 128x64, BK=32; 8 warps as 4x2, warp tile 32x32.
// Register double-buffered global loads.
// ---------------------------------------------------------------------------
__global__ __launch_bounds__(256) void proj_kernel(
    const float* __restrict__ Q,
    const float* __restrict__ Wq, const float* __restrict__ bq,
    const float* __restrict__ Wk, const float* __restrict__ bk,
    const float* __restrict__ Wv, const float* __restrict__ bv)
{
    __shared__ unsigned As[128*36];
    __shared__ unsigned Bs[64*36];

    const int z = blockIdx.z;
    const float* W    = (z==0) ? Wq : (z==1) ? Wk : Wv;
    const float* bias = (z==0) ? bq : (z==1) ? bk : bv;
    float*       out  = (z==0) ? g_q : (z==1) ? g_k : g_v;

    const int m0 = blockIdx.y * 128, n0 = blockIdx.x * 64;
    const int tid = threadIdx.x, warp = tid >> 5, lane = tid & 31;
    const int wm = warp >> 1, wn = warp & 1;

    float acc[2][4][4];
    #pragma unroll
    for (int i=0;i<2;i++)
        #pragma unroll
        for (int j=0;j<4;j++)
            #pragma unroll
            for (int r=0;r<4;r++) acc[i][j][r] = 0.f;

    const int ar = tid >> 3, ac = (tid & 7) * 4;

    float4 pa[4], pb[2];
    #pragma unroll
    for (int i = 0; i < 4; i++)
        pa[i] = *(const float4*)(Q + (size_t)(m0 + ar + i*32)*DM + ac);
    #pragma unroll
    for (int i = 0; i < 2; i++)
        pb[i] = *(const float4*)(W + (size_t)(n0 + ar + i*32)*DM + ac);

    for (int kt = 0; kt < DM; kt += 32){
        __syncthreads();
        #pragma unroll
        for (int i = 0; i < 4; i++)
            *(uint4*)&As[(ar + i*32)*36 + ac] = f2tf4(pa[i]);
        #pragma unroll
        for (int i = 0; i < 2; i++)
            *(uint4*)&Bs[(ar + i*32)*36 + ac] = f2tf4(pb[i]);
        __syncthreads();
        if (kt + 32 < DM){
            #pragma unroll
            for (int i = 0; i < 4; i++)
                pa[i] = *(const float4*)(Q + (size_t)(m0 + ar + i*32)*DM + kt + 32 + ac);
            #pragma unroll
            for (int i = 0; i < 2; i++)
                pb[i] = *(const float4*)(W + (size_t)(n0 + ar + i*32)*DM + kt + 32 + ac);
        }
        #pragma unroll
        for (int ks = 0; ks < 32; ks += 8){
            unsigned a[2][4], b[4][2];
            const int cb = ks + (lane & 3);
            #pragma unroll
            for (int mi = 0; mi < 2; mi++){
                int r0 = wm*32 + mi*16 + (lane >> 2);
                a[mi][0] = As[ r0   *36 + cb];
                a[mi][1] = As[(r0+8)*36 + cb];
                a[mi][2] = As[ r0   *36 + cb + 4];
                a[mi][3] = As[(r0+8)*36 + cb + 4];
            }
            #pragma unroll
            for (int ni = 0; ni < 4; ni++){
                int c0 = wn*32 + ni*8 + (lane >> 2);
                b[ni][0] = Bs[c0*36 + cb];
                b[ni][1] = Bs[c0*36 + cb + 4];
            }
            #pragma unroll
            for (int mi = 0; mi < 2; mi++)
                #pragma unroll
                for (int ni = 0; ni < 4; ni++)
                    mma8(acc[mi][ni], a[mi], b[ni]);
        }
    }

    #pragma unroll
    for (int mi = 0; mi < 2; mi++){
        #pragma unroll
        for (int ni = 0; ni < 4; ni++){
            int row = m0 + wm*32 + mi*16 + (lane >> 2);
            int col = n0 + wn*32 + ni*8 + (lane & 3)*2;
            float b0 = __ldg(bias + col), b1 = __ldg(bias + col + 1);
            *(float2*)(out + (size_t)row*DM + col) =
                make_float2(fmaxf(acc[mi][ni][0] + b0, 0.f),
                            fmaxf(acc[mi][ni][1] + b1, 0.f));
            *(float2*)(out + (size_t)(row+8)*DM + col) =
                make_float2(fmaxf(acc[mi][ni][2] + b0, 0.f),
                            fmaxf(acc[mi][ni][3] + b1, 0.f));
        }
    }
}

// ---------------------------------------------------------------------------
// Kernel 3: scores + softmax + weights write, per (b, h, 32-row q-tile)
// K tile 256 rows, reg double-buffered. 8 warps, warp tile 32x32.
// ---------------------------------------------------------------------------
__global__ __launch_bounds__(256) void score_kernel(float* __restrict__ wout){
    extern __shared__ unsigned smem[];
    unsigned* sQ  = smem;                        // 32 * 68
    unsigned* sK  = sQ + 32*SQ_STR;              // 256 * 68
    float*    sS  = (float*)(sK + 256*SQ_STR);   // 32 * 1028
    int*      sVK = (int*)(sS + 32*SS_STR);      // 1024
    int*      sVQ = sVK + SEQ;                   // 32

    const int b = blockIdx.z, h = blockIdx.y;
    const int q0 = blockIdx.x * 32;
    const int tid = threadIdx.x, warp = tid >> 5, lane = tid & 31;
    const int rowbase = b * SEQ;

    // load Q tile [32 x 64] (tf32)
    for (int i = tid; i < 512; i += 256){
        int r = i >> 4, c = (i & 15) * 4;
        float4 v = *(const float4*)(g_q + (size_t)(rowbase + q0 + r)*DM + h*HD + c);
        *(uint4*)&sQ[r*SQ_STR + c] = f2tf4(v);
    }
    for (int i = tid; i < SEQ; i += 256) sVK[i] = g_valid[rowbase + i];
    if (tid < 32) sVQ[tid] = g_valid[rowbase + q0 + tid];

    // prefetch K tile 0 (256 rows x 64 cols) into regs
    float4 pf[16];
    #pragma unroll
    for (int t = 0; t < 16; t++){
        int idx = tid + t*256, r = idx >> 4, c = (idx & 15) * 4;
        pf[t] = *(const float4*)(g_k + (size_t)(rowbase + r)*DM + h*HD + c);
    }

    for (int kt = 0; kt < 4; kt++){
        const int k0 = kt * 256;
        __syncthreads();
        #pragma unroll
        for (int t = 0; t < 16; t++){
            int idx = tid + t*256, r = idx >> 4, c = (idx & 15) * 4;
            *(uint4*)&sK[r*SQ_STR + c] = f2tf4(pf[t]);
        }
        __syncthreads();
        if (kt < 3){
            #pragma unroll
            for (int t = 0; t < 16; t++){
                int idx = tid + t*256, r = idx >> 4, c = (idx & 15) * 4;
                pf[t] = *(const float4*)(g_k + (size_t)(rowbase + k0 + 256 + r)*DM + h*HD + c);
            }
        }

        float acc[2][4][4];
        #pragma unroll
        for (int i=0;i<2;i++)
            #pragma unroll
            for (int j=0;j<4;j++)
                #pragma unroll
                for (int r=0;r<4;r++) acc[i][j][r] = 0.f;

        #pragma unroll
        for (int ks = 0; ks < 64; ks += 8){
            const int cb = ks + (lane & 3);
            unsigned a[2][4];
            #pragma unroll
            for (int mi = 0; mi < 2; mi++){
                int r0 = mi*16 + (lane >> 2);
                a[mi][0] = sQ[ r0   *SQ_STR + cb];
                a[mi][1] = sQ[(r0+8)*SQ_STR + cb];
                a[mi][2] = sQ[ r0   *SQ_STR + cb + 4];
                a[mi][3] = sQ[(r0+8)*SQ_STR + cb + 4];
            }
            #pragma unroll
            for (int ni = 0; ni < 4; ni++){
                int c0 = warp*32 + ni*8 + (lane >> 2);
                unsigned bf[2] = { sK[c0*SQ_STR + cb], sK[c0*SQ_STR + cb + 4] };
                mma8(acc[0][ni], a[0], bf);
                mma8(acc[1][ni], a[1], bf);
            }
        }
        #pragma unroll
        for (int mi = 0; mi < 2; mi++){
            #pragma unroll
            for (int ni = 0; ni < 4; ni++){
                int r  = mi*16 + (lane >> 2);
                int cl = warp*32 + ni*8 + (lane & 3)*2;
                bool v0 = sVK[k0 + cl] != 0, v1 = sVK[k0 + cl + 1] != 0;
                sS[ r   *SS_STR + k0 + cl    ] = v0 ? acc[mi][ni][0]*0.125f : NEGINF;
                sS[ r   *SS_STR + k0 + cl + 1] = v1 ? acc[mi][ni][1]*0.125f : NEGINF;
                sS[(r+8)*SS_STR + k0 + cl    ] = v0 ? acc[mi][ni][2]*0.125f : NEGINF;
                sS[(r+8)*SS_STR + k0 + cl + 1] = v1 ? acc[mi][ni][3]*0.125f : NEGINF;
            }
        }
    }
    __syncthreads();

    // softmax: one warp owns 4 rows; write normalized weights to global
    #pragma unroll 1
    for (int rr = 0; rr < 4; rr++){
        int r = warp*4 + rr;
        float* srow = sS + r*SS_STR;
        bool vq = sVQ[r] != 0;
        float vals[32];
        float m = NEGINF;
        #pragma unroll
        for (int j = 0; j < 32; j++){ vals[j] = srow[lane + j*32]; m = fmaxf(m, vals[j]); }
        #pragma unroll
        for (int o = 16; o > 0; o >>= 1) m = fmaxf(m, __shfl_xor_sync(0xffffffffu, m, o));
        float sum = 0.f;
        #pragma unroll
        for (int j = 0; j < 32; j++){ float p = __expf(vals[j] - m); vals[j] = p; sum += p; }
        #pragma unroll
        for (int o = 16; o > 0; o >>= 1) sum += __shfl_xor_sync(0xffffffffu, sum, o);
        float rs = vq ? (1.f / sum) : 0.f;    // invalid q-row: nan_to_num -> 0
        float* gw = wout + ((size_t)((b*NH + h)*SEQ + q0 + r)) * SEQ;
        #pragma unroll
        for (int j = 0; j < 32; j++) gw[lane + j*32] = vals[j] * rs;
    }
}

// ---------------------------------------------------------------------------
// Kernel 4: attn = W @ V + residual (reads weights from d_out)
// Per (b,h): [1024x1024]@[1024x64]. Block 128x64, k-tile 64, 8 warps 4x2,
// warp tile 32x32. V kept in [k][n] layout, stride 72 (conflict-free).
// ---------------------------------------------------------------------------
__global__ __launch_bounds__(256) void wv_kernel(const float* __restrict__ wout){
    extern __shared__ unsigned smem[];
    unsigned* sW = smem;              // 128 * 68  ([m][k], tf32)
    unsigned* sV = sW + 128*SQ_STR;   // 64 * 72   ([k][n], tf32)

    const int b = blockIdx.z, h = blockIdx.y;
    const int m0 = blockIdx.x * 128;
    const int tid = threadIdx.x, warp = tid >> 5, lane = tid & 31;
    const int rowbase = b * SEQ;
    const int wm = warp >> 1, wn = warp & 1;
    const float* Wg = wout + (size_t)((b*NH + h)*SEQ + m0) * SEQ;

    float acc[2][4][4];
    #pragma unroll
    for (int i=0;i<2;i++)
        #pragma unroll
        for (int j=0;j<4;j++)
            #pragma unroll
            for (int r=0;r<4;r++) acc[i][j][r] = 0.f;

    float4 pw[8], pv[4];
    #pragma unroll
    for (int t = 0; t < 8; t++){
        int idx = tid + t*256, r = idx >> 4, c = (idx & 15) * 4;
        pw[t] = *(const float4*)(Wg + (size_t)r*SEQ + c);
    }
    #pragma unroll
    for (int t = 0; t < 4; t++){
        int idx = tid + t*256, r = idx >> 4, c = (idx & 15) * 4;
        pv[t] = *(const float4*)(g_v + (size_t)(rowbase + r)*DM + h*HD + c);
    }

    for (int kt = 0; kt < 16; kt++){
        const int k0 = kt * 64;
        __syncthreads();
        #pragma unroll
        for (int t = 0; t < 8; t++){
            int idx = tid + t*256, r = idx >> 4, c = (idx & 15) * 4;
            *(uint4*)&sW[r*SQ_STR + c] = f2tf4(pw[t]);
        }
        #pragma unroll
        for (int t = 0; t < 4; t++){
            int idx = tid + t*256, r = idx >> 4, c = (idx & 15) * 4;
            *(uint4*)&sV[r*SV_STR + c] = f2tf4(pv[t]);
        }
        __syncthreads();
        if (kt < 15){
            #pragma unroll
            for (int t = 0; t < 8; t++){
                int idx = tid + t*256, r = idx >> 4, c = (idx & 15) * 4;
                pw[t] = *(const float4*)(Wg + (size_t)r*SEQ + k0 + 64 + c);
            }
            #pragma unroll
            for (int t = 0; t < 4; t++){
                int idx = tid + t*256, r = idx >> 4, c = (idx & 15) * 4;
                pv[t] = *(const float4*)(g_v + (size_t)(rowbase + k0 + 64 + r)*DM + h*HD + c);
            }
        }
        #pragma unroll
        for (int ks = 0; ks < 64; ks += 8){
            const int cb = ks + (lane & 3);
            unsigned a[2][4];
            #pragma unroll
            for (int mi = 0; mi < 2; mi++){
                int r0 = wm*32 + mi*16 + (lane >> 2);
                a[mi][0] = sW[ r0   *SQ_STR + cb];
                a[mi][1] = sW[(r0+8)*SQ_STR + cb];
                a[mi][2] = sW[ r0   *SQ_STR + cb + 4];
                a[mi][3] = sW[(r0+8)*SQ_STR + cb + 4];
            }
            #pragma unroll
            for (int ni = 0; ni < 4; ni++){
                int c0 = wn*32 + ni*8 + (lane >> 2);
                unsigned bf[2] = { sV[cb*SV_STR + c0], sV[(cb+4)*SV_STR + c0] };
                mma8(acc[0][ni], a[0], bf);
                mma8(acc[1][ni], a[1], bf);
            }
        }
    }

    #pragma unroll
    for (int mi = 0; mi < 2; mi++){
        #pragma unroll
        for (int ni = 0; ni < 4; ni++){
            int r  = m0 + wm*32 + mi*16 + (lane >> 2);
            int cl = h*HD + wn*32 + ni*8 + (lane & 3)*2;
            size_t base = (size_t)(rowbase + r)*DM + cl;
            float2 q0v = *(const float2*)(g_q + base);
            float2 q1v = *(const float2*)(g_q + base + 8*DM);
            *(float2*)(g_att + base)        = make_float2(acc[mi][ni][0] + q0v.x, acc[mi][ni][1] + q0v.y);
            *(float2*)(g_att + base + 8*DM) = make_float2(acc[mi][ni][2] + q1v.x, acc[mi][ni][3] + q1v.y);
        }
    }
}

// ---------------------------------------------------------------------------
// Kernel 5: LayerNorm + relu, one block (128 thr) per row
// ---------------------------------------------------------------------------
__global__ __launch_bounds__(128) void ln_kernel(const float* __restrict__ lnw,
                                                 const float* __restrict__ lnb,
                                                 float* __restrict__ out){
    const int row = blockIdx.x, tid = threadIdx.x;
    const float4 x = *(const float4*)(g_att + (size_t)row*DM + tid*4);
    float s  = x.x + x.y + x.z + x.w;
    float ss = fmaf(x.x, x.x, fmaf(x.y, x.y, fmaf(x.z, x.z, x.w*x.w)));
    #pragma unroll
    for (int o = 16; o > 0; o >>= 1){
        s  += __shfl_xor_sync(0xffffffffu, s,  o);
        ss += __shfl_xor_sync(0xffffffffu, ss, o);
    }
    __shared__ float red[8];
    int warp = tid >> 5, lane = tid & 31;
    if (lane == 0){ red[warp] = s; red[warp+4] = ss; }
    __syncthreads();
    s  = red[0] + red[1] + red[2] + red[3];
    ss = red[4] + red[5] + red[6] + red[7];
    float mu  = s * (1.0f/DM);
    float inv = rsqrtf(ss * (1.0f/DM) - mu*mu + 1e-5f);
    const float4 w = *(const float4*)(lnw + tid*4);
    const float4 bb = *(const float4*)(lnb + tid*4);
    float4 y;
    y.x = fmaxf((x.x - mu)*inv*w.x + bb.x, 0.f);
    y.y = fmaxf((x.y - mu)*inv*w.y + bb.y, 0.f);
    y.z = fmaxf((x.z - mu)*inv*w.z + bb.z, 0.f);
    y.w = fmaxf((x.w - mu)*inv*w.w + bb.w, 0.f);
    *(float4*)(out + (size_t)row*DM + tid*4) = y;
}

// ---------------------------------------------------------------------------
extern "C" void kernel_launch(void* const* d_in, const int* in_sizes, int n_in,
                              void* d_out, int out_size){
    const float* Q   = (const float*)d_in[0];
    const float* Wq  = (const float*)d_in[1];
    const float* bq  = (const float*)d_in[2];
    const float* Wk  = (const float*)d_in[3];
    const float* bk  = (const float*)d_in[4];
    const float* Wv  = (const float*)d_in[5];
    const float* bv  = (const float*)d_in[6];
    const float* lnw = (const float*)d_in[7];
    const float* lnb = (const float*)d_in[8];
    float* out = (float*)d_out;

    valid_kernel<<<NROWS/8, 256>>>(Q);
    proj_kernel<<<dim3(8, 128, 3), 256>>>(Q, Wq, bq, Wk, bk, Wv, bv);

    const int score_smem = (32*SQ_STR + 256*SQ_STR + 32*SS_STR + SEQ + 32) * 4;  // 214144
    cudaFuncSetAttribute(score_kernel, cudaFuncAttributeMaxDynamicSharedMemorySize, score_smem);
    score_kernel<<<dim3(SEQ/32, NH, NB), 256, score_smem>>>(out + OUT0);

    const int wv_smem = (128*SQ_STR + 64*SV_STR) * 4;  // 53248
    cudaFuncSetAttribute(wv_kernel, cudaFuncAttributeMaxDynamicSharedMemorySize, wv_smem);
    wv_kernel<<<dim3(SEQ/128, NH, NB), 256, wv_smem>>>(out + OUT0);

    ln_kernel<<<NROWS, 128>>>(lnw, lnb, out);
}